// round 2
// baseline (speedup 1.0000x reference)
#include <cuda_runtime.h>

#define NN 100000
#define NE 1600000
#define KF 1433
#define NEG 0.2f

// ---------------- scratch (device globals; no allocation allowed) ----------
__device__ float g_feat1[NN * 64];   // features @ W1
__device__ float g_el1[NN * 8];
__device__ float g_er1[NN * 8];
__device__ float g_denom1[NN * 8];
__device__ float g_numer1[NN * 64];
__device__ float g_feat2p[NN * 8];   // [0..6]=feat2, [7]=1.0
__device__ float g_el2[NN];
__device__ float g_er2[NN];
__device__ float g_acc2[NN * 8];     // [0..6]=numer2, [7]=denom2

// ---------------- helpers --------------------------------------------------
__device__ __forceinline__ unsigned long long pk2(float lo, float hi) {
    unsigned long long r;
    asm("mov.b64 %0, {%1, %2};" : "=l"(r) : "f"(lo), "f"(hi));
    return r;
}
__device__ __forceinline__ void upk2(unsigned long long v, float& lo, float& hi) {
    asm("mov.b64 {%0, %1}, %2;" : "=f"(lo), "=f"(hi) : "l"(v));
}
// packed fp32x2 FMA (sm_100+): doubles fp32 FMA throughput vs FFMA
__device__ __forceinline__ void fma2(unsigned long long& c, unsigned long long a,
                                     unsigned long long b) {
    asm("fma.rn.f32x2 %0, %1, %2, %0;" : "+l"(c) : "l"(a), "l"(b));
}
// vector float4 reduction (sm_90+)
__device__ __forceinline__ void red_add_v4(float* p, float x, float y, float z, float w) {
    asm volatile("red.global.add.v4.f32 [%0], {%1, %2, %3, %4};"
                 :: "l"(p), "f"(x), "f"(y), "f"(z), "f"(w) : "memory");
}
__device__ __forceinline__ float lrelu(float x) { return x >= 0.f ? x : NEG * x; }

// ---------------- K0: zero layer-1 accumulators ----------------------------
__global__ void init_kernel() {
    int i = blockIdx.x * blockDim.x + threadIdx.x;
    float4 z = make_float4(0.f, 0.f, 0.f, 0.f);
    if (i < NN * 16) ((float4*)g_numer1)[i] = z;   // 64 floats/node
    if (i < NN * 2)  ((float4*)g_denom1)[i] = z;   // 8 floats/node
}

// ---------------- K1: feat1 = features @ W1 (fp32x2-packed SIMT GEMM) ------
// BM=128, BN=64(full), BK=16; 256 threads; 8x4 micro-tile per thread.
__global__ __launch_bounds__(256) void gemm1_kernel(const float* __restrict__ A,
                                                    const float* __restrict__ W) {
    __shared__ float As[16][132];  // [k][m], padded
    __shared__ float Bs[16][64];   // [k][n]
    const int bm  = blockIdx.x * 128;
    const int tid = threadIdx.x;
    const int tx  = tid & 15;      // col group (4 cols)
    const int ty  = tid >> 4;      // row group (4+4 rows)

    unsigned long long acc[8][2];
#pragma unroll
    for (int r = 0; r < 8; r++) { acc[r][0] = 0ull; acc[r][1] = 0ull; }

    for (int k0 = 0; k0 < KF; k0 += 16) {
        // load A tile (128x16), transposed into As[k][m]
#pragma unroll
        for (int j = 0; j < 8; j++) {
            int i = tid + j * 256;
            int m = i >> 4, kk = i & 15;
            int row = bm + m, col = k0 + kk;
            float v = (row < NN && col < KF) ? A[row * KF + col] : 0.f;
            As[kk][m] = v;
        }
        // load W tile (16x64)
#pragma unroll
        for (int j = 0; j < 4; j++) {
            int i = tid + j * 256;
            int kk = i >> 6, n = i & 63;
            int col = k0 + kk;
            Bs[kk][n] = (col < KF) ? W[col * 64 + n] : 0.f;
        }
        __syncthreads();
#pragma unroll
        for (int kk = 0; kk < 16; kk++) {
            float4 a0 = *(const float4*)&As[kk][ty * 4];
            float4 a1 = *(const float4*)&As[kk][64 + ty * 4];
            float4 b  = *(const float4*)&Bs[kk][tx * 4];
            unsigned long long b01 = pk2(b.x, b.y);
            unsigned long long b23 = pk2(b.z, b.w);
            float ar[8] = {a0.x, a0.y, a0.z, a0.w, a1.x, a1.y, a1.z, a1.w};
#pragma unroll
            for (int r = 0; r < 8; r++) {
                unsigned long long aa = pk2(ar[r], ar[r]);
                fma2(acc[r][0], aa, b01);
                fma2(acc[r][1], aa, b23);
            }
        }
        __syncthreads();
    }
#pragma unroll
    for (int r = 0; r < 8; r++) {
        int row = bm + ((r < 4) ? (ty * 4 + r) : (64 + ty * 4 + (r - 4)));
        if (row < NN) {
            float c0, c1, c2, c3;
            upk2(acc[r][0], c0, c1);
            upk2(acc[r][1], c2, c3);
            *(float4*)&g_feat1[row * 64 + tx * 4] = make_float4(c0, c1, c2, c3);
        }
    }
}

// ---------------- K1b: el/er per (node, head) ------------------------------
__global__ void elr_kernel(const float* __restrict__ al, const float* __restrict__ ar) {
    int t = blockIdx.x * blockDim.x + threadIdx.x;
    if (t >= NN * 8) return;
    int n = t >> 3, h = t & 7;
    const float4* f = (const float4*)&g_feat1[n * 64 + h * 8];
    float4 f0 = f[0], f1 = f[1];
    const float4* l4 = (const float4*)&al[h * 8];
    const float4* r4 = (const float4*)&ar[h * 8];
    float4 l0 = l4[0], l1 = l4[1];
    float4 r0 = r4[0], r1 = r4[1];
    float el = f0.x * l0.x + f0.y * l0.y + f0.z * l0.z + f0.w * l0.w +
               f1.x * l1.x + f1.y * l1.y + f1.z * l1.z + f1.w * l1.w;
    float er = f0.x * r0.x + f0.y * r0.y + f0.z * r0.z + f0.w * r0.w +
               f1.x * r1.x + f1.y * r1.y + f1.z * r1.z + f1.w * r1.w;
    g_el1[t] = el;
    g_er1[t] = er;
}

// ---------------- K2: layer-1 edge pass (no segment_max needed) ------------
// exp(e-emax)/sum == exp(e)/sum mathematically; |e| <= ~6 so fp32 exp is safe.
__global__ void edge1_kernel(const int* __restrict__ src, const int* __restrict__ dst) {
    int t = blockIdx.x * blockDim.x + threadIdx.x;
    int e = t >> 3;
    if (e >= NE) return;
    int h = t & 7;
    int s = __ldg(&src[e]);
    int d = __ldg(&dst[e]);
    float x = g_el1[s * 8 + h] + g_er1[d * 8 + h];
    float ex = __expf(lrelu(x));
    atomicAdd(&g_denom1[d * 8 + h], ex);
    const float4* f = (const float4*)&g_feat1[s * 64 + h * 8];
    float4 a = f[0], b = f[1];
    red_add_v4(&g_numer1[d * 64 + h * 8],     ex * a.x, ex * a.y, ex * a.z, ex * a.w);
    red_add_v4(&g_numer1[d * 64 + h * 8 + 4], ex * b.x, ex * b.y, ex * b.z, ex * b.w);
}

// ---------------- K3: finalize layer1 + MHI pooling + layer2 features ------
__global__ __launch_bounds__(256) void node_kernel(
    const float* __restrict__ b1, const float* __restrict__ Wm,
    const float* __restrict__ bm, const float* __restrict__ a,
    const float* __restrict__ W2, const float* __restrict__ al2,
    const float* __restrict__ ar2) {
    int n = blockIdx.x * blockDim.x + threadIdx.x;
    if (n >= NN) return;

    float x[8][8];
#pragma unroll
    for (int h = 0; h < 8; h++) {
        float dn  = g_denom1[n * 8 + h];
        float inv = dn > 0.f ? 1.f / dn : 0.f;
#pragma unroll
        for (int o = 0; o < 8; o++) {
            float v = g_numer1[n * 64 + h * 8 + o] * inv + __ldg(&b1[h * 8 + o]);
            x[h][o] = v > 0.f ? v : 0.f;
        }
    }
    // MHI attention pooling over heads
    float xm[8], eh[8];
#pragma unroll
    for (int i = 0; i < 8; i++) xm[i] = 0.f;
#pragma unroll
    for (int h = 0; h < 8; h++) {
        float s = 0.f;
#pragma unroll
        for (int i = 0; i < 8; i++) {
            float xl = __ldg(&bm[i]);
#pragma unroll
            for (int j = 0; j < 8; j++) xl += x[h][j] * __ldg(&Wm[i * 8 + j]);
            xm[i] += xl;
            s += xl * __ldg(&a[i]);
        }
        eh[h] = s;
    }
    float ebar = 0.f;
#pragma unroll
    for (int i = 0; i < 8; i++) ebar += (xm[i] * 0.125f) * __ldg(&a[8 + i]);
    float ssum = 0.f;
#pragma unroll
    for (int h = 0; h < 8; h++) {
        float v = eh[h] + ebar;
        v = v > 0.f ? v : 0.f;      // relu
        v = __expf(v);              // softmax over heads (e >= 0, small)
        eh[h] = v;
        ssum += v;
    }
    float rs = 1.f / ssum;
    float hv[8];
#pragma unroll
    for (int m = 0; m < 8; m++) {
        float s = 0.f;
#pragma unroll
        for (int h = 0; h < 8; h++) s += x[h][m] * eh[h];
        hv[m] = s * rs;
    }
    // layer 2: feat2 = hv @ W2, el2/er2
    float f2[8];
#pragma unroll
    for (int o = 0; o < 7; o++) {
        float s = 0.f;
#pragma unroll
        for (int m = 0; m < 8; m++) s += hv[m] * __ldg(&W2[m * 7 + o]);
        f2[o] = s;
    }
    f2[7] = 1.f;  // lane 7 carries the softmax denominator through the v4 RED
    float el = 0.f, er = 0.f;
#pragma unroll
    for (int o = 0; o < 7; o++) {
        el += f2[o] * __ldg(&al2[o]);
        er += f2[o] * __ldg(&ar2[o]);
    }
    float4* out4 = (float4*)&g_feat2p[n * 8];
    out4[0] = make_float4(f2[0], f2[1], f2[2], f2[3]);
    out4[1] = make_float4(f2[4], f2[5], f2[6], f2[7]);
    g_el2[n] = el;
    g_er2[n] = er;
    float4* acc = (float4*)&g_acc2[n * 8];
    acc[0] = make_float4(0.f, 0.f, 0.f, 0.f);
    acc[1] = make_float4(0.f, 0.f, 0.f, 0.f);
}

// ---------------- K4: layer-2 edge pass ------------------------------------
__global__ void edge2_kernel(const int* __restrict__ src, const int* __restrict__ dst) {
    int e = blockIdx.x * blockDim.x + threadIdx.x;
    if (e >= NE) return;
    int s = __ldg(&src[e]);
    int d = __ldg(&dst[e]);
    float xx = g_el2[s] + g_er2[d];
    float ex = __expf(lrelu(xx));
    const float4* f = (const float4*)&g_feat2p[s * 8];
    float4 a = f[0], b = f[1];
    red_add_v4(&g_acc2[d * 8],     ex * a.x, ex * a.y, ex * a.z, ex * a.w);
    red_add_v4(&g_acc2[d * 8 + 4], ex * b.x, ex * b.y, ex * b.z, ex * b.w);
}

// ---------------- K5: final output -----------------------------------------
__global__ void final_kernel(const float* __restrict__ b2, float* __restrict__ out) {
    int t = blockIdx.x * blockDim.x + threadIdx.x;
    if (t >= NN * 7) return;
    int n = t / 7, o = t - n * 7;
    float dn = g_acc2[n * 8 + 7];
    float v  = dn > 0.f ? g_acc2[n * 8 + o] / dn : 0.f;
    out[t] = v + __ldg(&b2[o]);
}

// ---------------- launch ----------------------------------------------------
extern "C" void kernel_launch(void* const* d_in, const int* in_sizes, int n_in,
                              void* d_out, int out_size) {
    const float* features = (const float*)d_in[0];
    const int*   src      = (const int*)d_in[1];
    const int*   dst      = (const int*)d_in[2];
    const float* W1       = (const float*)d_in[3];
    const float* attn_l1  = (const float*)d_in[4];
    const float* attn_r1  = (const float*)d_in[5];
    const float* b1       = (const float*)d_in[6];
    const float* Wm       = (const float*)d_in[7];
    const float* bm       = (const float*)d_in[8];
    const float* a        = (const float*)d_in[9];
    const float* W2       = (const float*)d_in[10];
    const float* attn_l2  = (const float*)d_in[11];
    const float* attn_r2  = (const float*)d_in[12];
    const float* b2       = (const float*)d_in[13];
    float* out = (float*)d_out;

    init_kernel<<<(NN * 16 + 255) / 256, 256>>>();
    gemm1_kernel<<<(NN + 127) / 128, 256>>>(features, W1);
    elr_kernel<<<(NN * 8 + 255) / 256, 256>>>(attn_l1, attn_r1);
    edge1_kernel<<<(NE * 8 + 255) / 256, 256>>>(src, dst);
    node_kernel<<<(NN + 255) / 256, 256>>>(b1, Wm, bm, a, W2, attn_l2, attn_r2);
    edge2_kernel<<<(NE + 255) / 256, 256>>>(src, dst);
    final_kernel<<<(NN * 7 + 255) / 256, 256>>>(b2, out);
}